// round 6
// baseline (speedup 1.0000x reference)
#include <cuda_runtime.h>
#include <cuda_bf16.h>
#include <cstdint>

#define NB   32
#define SS   2048
#define SPAD 2064
#define CI   256
#define CO   256
#define KW   16
#define TOUT 2033

#define MT   128           // t rows per CTA
#define NT   128           // o cols per CTA
#define ICH  32            // i-channels per reduction chunk
#define NIC  (CI / ICH)    // 8
#define AROWS 143          // x rows per chunk (128 + 15)

#define ASTRIDE 80         // bytes/row in smem (32 bf16 = 64B + 16B pad)
#define BSTRIDE 80

#define A_LO_OFF (144 * ASTRIDE)            // 11520
#define A_BYTES  (2 * 144 * ASTRIDE)        // 23040
#define B_OFF    A_BYTES
#define B_LO_OFF (128 * BSTRIDE)            // within a stage
#define B_STAGE  (2 * 128 * BSTRIDE)        // 20480 (hi+lo)
#define SMEM_TOTAL (A_BYTES + 2 * B_STAGE)  // 64000

#define NTHREADS 512

// ---------------- device scratch ----------------
__device__ __nv_bfloat16 g_xhi[(size_t)NB * SPAD * CI];
__device__ __nv_bfloat16 g_xlo[(size_t)NB * SPAD * CI];
__device__ __nv_bfloat16 g_whi[(size_t)KW * CO * CI];   // [k][o][i]
__device__ __nv_bfloat16 g_wlo[(size_t)KW * CO * CI];

// ---------------- helpers ----------------
__device__ __forceinline__ uint32_t s2u(const void* p) {
    uint32_t a;
    asm("{ .reg .u64 t; cvta.to.shared.u64 t, %1; cvt.u32.u64 %0, t; }"
        : "=r"(a) : "l"(p));
    return a;
}
__device__ __forceinline__ void cp16(uint32_t d, const void* s) {
    asm volatile("cp.async.cg.shared.global [%0], [%1], 16;" :: "r"(d), "l"(s));
}
__device__ __forceinline__ void cp_commit() {
    asm volatile("cp.async.commit_group;" ::: "memory");
}
__device__ __forceinline__ void cp_wait1() {
    asm volatile("cp.async.wait_group 1;" ::: "memory");
}
__device__ __forceinline__ void cp_wait0() {
    asm volatile("cp.async.wait_group 0;" ::: "memory");
}
__device__ __forceinline__ void ldm_x4(uint32_t* r, uint32_t a) {
    asm volatile("ldmatrix.sync.aligned.m8n8.x4.shared.b16 {%0,%1,%2,%3}, [%4];"
                 : "=r"(r[0]), "=r"(r[1]), "=r"(r[2]), "=r"(r[3]) : "r"(a));
}
__device__ __forceinline__ void mma16816(float* c, const uint32_t* a, const uint32_t* b) {
    asm volatile(
        "mma.sync.aligned.m16n8k16.row.col.f32.bf16.bf16.f32 "
        "{%0,%1,%2,%3}, {%4,%5,%6,%7}, {%8,%9}, {%0,%1,%2,%3};"
        : "+f"(c[0]), "+f"(c[1]), "+f"(c[2]), "+f"(c[3])
        : "r"(a[0]), "r"(a[1]), "r"(a[2]), "r"(a[3]), "r"(b[0]), "r"(b[1]));
}

// ---------------- fused prep kernel ----------------
#define XBLOCKS 16512      // NB*SPAD*CI/4 / 256
#define WBLOCKS 4096       // KW*CO*CI / 256

__global__ void prep_kernel(const float* __restrict__ x,
                            const float* __restrict__ wr,
                            const float* __restrict__ wi,
                            const float* __restrict__ ph) {
    if (blockIdx.x < XBLOCKS) {
        size_t idx4 = (size_t)blockIdx.x * 256 + threadIdx.x;
        size_t idx = idx4 * 4;
        int i = idx & (CI - 1);
        size_t r = idx >> 8;
        int t = (int)(r % SPAD);
        int b = (int)(r / SPAD);
        float4 v = make_float4(0.f, 0.f, 0.f, 0.f);
        if (t < SS)
            v = *reinterpret_cast<const float4*>(x + ((size_t)b * SS + t) * CI + i);
        __nv_bfloat16 h0 = __float2bfloat16(v.x), h1 = __float2bfloat16(v.y);
        __nv_bfloat16 h2 = __float2bfloat16(v.z), h3 = __float2bfloat16(v.w);
        __nv_bfloat162* hi = reinterpret_cast<__nv_bfloat162*>(g_xhi + idx);
        __nv_bfloat162* lo = reinterpret_cast<__nv_bfloat162*>(g_xlo + idx);
        hi[0] = __nv_bfloat162(h0, h1);
        hi[1] = __nv_bfloat162(h2, h3);
        lo[0] = __nv_bfloat162(__float2bfloat16(v.x - __bfloat162float(h0)),
                               __float2bfloat16(v.y - __bfloat162float(h1)));
        lo[1] = __nv_bfloat162(__float2bfloat16(v.z - __bfloat162float(h2)),
                               __float2bfloat16(v.w - __bfloat162float(h3)));
    } else {
        int idx = (blockIdx.x - XBLOCKS) * 256 + threadIdx.x;
        int i = idx & (CI - 1);
        int o = (idx >> 8) & (CO - 1);
        int k = idx >> 16;
        float s, c;
        sincosf(ph[k], &s, &c);
        int widx = (o * CI + i) * KW + k;        // w_real/w_imag are [o][i][k]
        float v = c * wr[widx] - s * wi[widx];
        __nv_bfloat16 h = __float2bfloat16(v);
        g_whi[idx] = h;
        g_wlo[idx] = __float2bfloat16(v - __bfloat162float(h));
    }
}

// ---------------- main HMMA kernel ----------------
__global__ __launch_bounds__(NTHREADS, 1)
void conv_mma_kernel(float* __restrict__ out) {
    extern __shared__ char smem[];
    const uint32_t sb = s2u(smem);
    const int tid = threadIdx.x;
    const int l = tid & 31, wid = tid >> 5;
    const int wm = wid & 3, wn = wid >> 2;      // warp grid 4(m) x 4(n)
    const int t0 = blockIdx.x * MT;
    const int b  = blockIdx.y;
    const int o0 = blockIdx.z * NT;

    const char* gxhi = (const char*)g_xhi;
    const char* gxlo = (const char*)g_xlo;
    const char* gwhi = (const char*)g_whi;
    const char* gwlo = (const char*)g_wlo;

    float acc[2][4][4];
#pragma unroll
    for (int mt = 0; mt < 2; mt++)
#pragma unroll
        for (int n = 0; n < 4; n++)
#pragma unroll
            for (int q = 0; q < 4; q++) acc[mt][n][q] = 0.f;

    // ldmatrix lane-address components
    const int lm = l & 15;                 // A: row within 16
    const int lg = l >> 4;                 // A: k-half (+16B)
    const int bo_row = (l & 7) + ((l >> 4) << 3);   // B: o-row within 16
    const int bhalf = (l >> 3) & 1;                 // B: k-half (+16B)

    for (int ic = 0; ic < NIC; ic++) {
        const size_t ioff = (size_t)ic * ICH * 2;   // byte offset into i dim

        // ---- A chunk (143 rows x 32 i, hi+lo), single-buffered ----
        for (int u = tid; u < AROWS * 4; u += NTHREADS) {
            int row = u >> 2, seg = u & 3;
            size_t g = ((size_t)(b * SPAD + t0 + row)) * (CI * 2) + ioff + seg * 16;
            uint32_t so = row * ASTRIDE + seg * 16;
            cp16(sb + so, gxhi + g);
            cp16(sb + A_LO_OFF + so, gxlo + g);
        }
        // ---- B[k=0] -> stage 0 ----
        {
            uint32_t bs = sb + B_OFF;
            int u = tid;
            int o = u >> 2, seg = u & 3;
            size_t g = ((size_t)(o0 + o)) * (CI * 2) + ioff + seg * 16;
            cp16(bs + o * BSTRIDE + seg * 16, gwhi + g);
            cp16(bs + B_LO_OFF + o * BSTRIDE + seg * 16, gwlo + g);
        }
        cp_commit();

        for (int k = 0; k < KW; k++) {
            const int s = k & 1;
            if (k + 1 < KW) {
                uint32_t bs = sb + B_OFF + (s ^ 1) * B_STAGE;
                int u = tid;
                int o = u >> 2, seg = u & 3;
                size_t g = ((size_t)((k + 1) * CO + o0 + o)) * (CI * 2) + ioff + seg * 16;
                cp16(bs + o * BSTRIDE + seg * 16, gwhi + g);
                cp16(bs + B_LO_OFF + o * BSTRIDE + seg * 16, gwlo + g);
                cp_commit();
                cp_wait1();
            } else {
                cp_wait0();
            }
            __syncthreads();

            const uint32_t a_base = sb + (uint32_t)(k + wm * 32 + lm) * ASTRIDE + lg * 16;
            const uint32_t b_base = sb + B_OFF + s * B_STAGE
                                  + (uint32_t)(wn * 32 + bo_row) * BSTRIDE + bhalf * 16;
#pragma unroll
            for (int ks = 0; ks < 2; ks++) {
                uint32_t ah[2][4], al[2][4];
#pragma unroll
                for (int mt = 0; mt < 2; mt++) {
                    uint32_t a0 = a_base + (uint32_t)(mt * 16) * ASTRIDE + ks * 32;
                    ldm_x4(ah[mt], a0);
                    ldm_x4(al[mt], a0 + A_LO_OFF);
                }
                uint32_t bh[2][4], bl[2][4];     // each x4 covers 2 n8-tiles
#pragma unroll
                for (int p = 0; p < 2; p++) {
                    uint32_t b0 = b_base + (uint32_t)(p * 16) * BSTRIDE + ks * 32;
                    ldm_x4(bh[p], b0);
                    ldm_x4(bl[p], b0 + B_LO_OFF);
                }
#pragma unroll
                for (int n = 0; n < 4; n++) {
                    const uint32_t* bhp = &bh[n >> 1][(n & 1) * 2];
                    const uint32_t* blp = &bl[n >> 1][(n & 1) * 2];
#pragma unroll
                    for (int mt = 0; mt < 2; mt++) {
                        mma16816(acc[mt][n], ah[mt], bhp);
                        mma16816(acc[mt][n], ah[mt], blp);
                        mma16816(acc[mt][n], al[mt], bhp);
                    }
                }
            }
            __syncthreads();
        }
    }

    // ---- epilogue: direct register -> gmem ----
    const int lr = l >> 2, lc = l & 3;
#pragma unroll
    for (int mt = 0; mt < 2; mt++) {
        int r0 = t0 + wm * 32 + mt * 16 + lr;
        int r1 = r0 + 8;
#pragma unroll
        for (int n = 0; n < 4; n++) {
            int o = o0 + wn * 32 + n * 8 + lc * 2;
            if (r0 < TOUT) {
                float2 v = make_float2(acc[mt][n][0], acc[mt][n][1]);
                *reinterpret_cast<float2*>(out + ((size_t)b * TOUT + r0) * CO + o) = v;
            }
            if (r1 < TOUT) {
                float2 v = make_float2(acc[mt][n][2], acc[mt][n][3]);
                *reinterpret_cast<float2*>(out + ((size_t)b * TOUT + r1) * CO + o) = v;
            }
        }
    }
}

// ---------------- launch ----------------
extern "C" void kernel_launch(void* const* d_in, const int* in_sizes, int n_in,
                              void* d_out, int out_size) {
    const float* x  = (const float*)d_in[0];
    const float* wr = (const float*)d_in[1];
    const float* wi = (const float*)d_in[2];
    const float* ph = (const float*)d_in[3];
    float* out = (float*)d_out;
    (void)in_sizes; (void)n_in; (void)out_size;

    cudaFuncSetAttribute(conv_mma_kernel,
                         cudaFuncAttributeMaxDynamicSharedMemorySize, SMEM_TOTAL);

    prep_kernel<<<XBLOCKS + WBLOCKS, 256>>>(x, wr, wi, ph);

    dim3 grid(SS / MT, NB, CO / NT);   // 16 x 32 x 2 = 1024 CTAs
    conv_mma_kernel<<<grid, NTHREADS, SMEM_TOTAL>>>(out);
}

// round 7
// speedup vs baseline: 1.2198x; 1.2198x over previous
#include <cuda_runtime.h>
#include <cuda_bf16.h>
#include <cstdint>

#define NB   32
#define SS   2048
#define SPAD 2064
#define CI   256
#define CO   256
#define KW   16
#define TOUT 2033

#define MT   128           // t rows per CTA
#define NT   128           // o cols per CTA
#define ICH  32            // i-channels per reduction chunk
#define NIC  (CI / ICH)    // 8
#define NITER (NIC * KW)   // 128 flat iterations
#define AROWS 143

#define ASTRIDE 80
#define BSTRIDE 80

#define A_LO   11520                 // 144*80, lo half within an A buffer
#define ABUF   23040                 // one A buffer (hi+lo)
#define B_OFF  46080                 // after 2 A buffers
#define BSTG   20480                 // one B stage (hi+lo)
#define B_LO   10240                 // lo half within a B stage
#define SMEM_TOTAL (B_OFF + 3 * BSTG)   // 107520

// ---------------- device scratch ----------------
__device__ __nv_bfloat16 g_xhi[(size_t)NB * SPAD * CI];
__device__ __nv_bfloat16 g_xlo[(size_t)NB * SPAD * CI];
__device__ __nv_bfloat16 g_whi[(size_t)KW * CO * CI];   // [k][o][i]
__device__ __nv_bfloat16 g_wlo[(size_t)KW * CO * CI];

// ---------------- helpers ----------------
__device__ __forceinline__ uint32_t s2u(const void* p) {
    uint32_t a;
    asm("{ .reg .u64 t; cvta.to.shared.u64 t, %1; cvt.u32.u64 %0, t; }"
        : "=r"(a) : "l"(p));
    return a;
}
__device__ __forceinline__ void cp16(uint32_t d, const void* s) {
    asm volatile("cp.async.cg.shared.global [%0], [%1], 16;" :: "r"(d), "l"(s));
}
__device__ __forceinline__ void cp_commit() {
    asm volatile("cp.async.commit_group;" ::: "memory");
}
__device__ __forceinline__ void cp_wait1() {
    asm volatile("cp.async.wait_group 1;" ::: "memory");
}
__device__ __forceinline__ void ldm_x4(uint32_t* r, uint32_t a) {
    asm volatile("ldmatrix.sync.aligned.m8n8.x4.shared.b16 {%0,%1,%2,%3}, [%4];"
                 : "=r"(r[0]), "=r"(r[1]), "=r"(r[2]), "=r"(r[3]) : "r"(a));
}
__device__ __forceinline__ void mma16816(float* c, const uint32_t* a, const uint32_t* b) {
    asm volatile(
        "mma.sync.aligned.m16n8k16.row.col.f32.bf16.bf16.f32 "
        "{%0,%1,%2,%3}, {%4,%5,%6,%7}, {%8,%9}, {%0,%1,%2,%3};"
        : "+f"(c[0]), "+f"(c[1]), "+f"(c[2]), "+f"(c[3])
        : "r"(a[0]), "r"(a[1]), "r"(a[2]), "r"(a[3]), "r"(b[0]), "r"(b[1]));
}

// ---------------- fused prep kernel ----------------
#define XBLOCKS 16512      // NB*SPAD*CI/4 / 256
#define WBLOCKS 4096       // KW*CO*CI / 256

__global__ void prep_kernel(const float* __restrict__ x,
                            const float* __restrict__ wr,
                            const float* __restrict__ wi,
                            const float* __restrict__ ph) {
    if (blockIdx.x < XBLOCKS) {
        size_t idx4 = (size_t)blockIdx.x * 256 + threadIdx.x;
        size_t idx = idx4 * 4;
        int i = idx & (CI - 1);
        size_t r = idx >> 8;
        int t = (int)(r % SPAD);
        int b = (int)(r / SPAD);
        float4 v = make_float4(0.f, 0.f, 0.f, 0.f);
        if (t < SS)
            v = *reinterpret_cast<const float4*>(x + ((size_t)b * SS + t) * CI + i);
        __nv_bfloat16 h0 = __float2bfloat16(v.x), h1 = __float2bfloat16(v.y);
        __nv_bfloat16 h2 = __float2bfloat16(v.z), h3 = __float2bfloat16(v.w);
        __nv_bfloat162* hi = reinterpret_cast<__nv_bfloat162*>(g_xhi + idx);
        __nv_bfloat162* lo = reinterpret_cast<__nv_bfloat162*>(g_xlo + idx);
        hi[0] = __nv_bfloat162(h0, h1);
        hi[1] = __nv_bfloat162(h2, h3);
        lo[0] = __nv_bfloat162(__float2bfloat16(v.x - __bfloat162float(h0)),
                               __float2bfloat16(v.y - __bfloat162float(h1)));
        lo[1] = __nv_bfloat162(__float2bfloat16(v.z - __bfloat162float(h2)),
                               __float2bfloat16(v.w - __bfloat162float(h3)));
    } else {
        int idx = (blockIdx.x - XBLOCKS) * 256 + threadIdx.x;
        int i = idx & (CI - 1);
        int o = (idx >> 8) & (CO - 1);
        int k = idx >> 16;
        float s, c;
        sincosf(ph[k], &s, &c);
        int widx = (o * CI + i) * KW + k;        // w_real/w_imag are [o][i][k]
        float v = c * wr[widx] - s * wi[widx];
        __nv_bfloat16 h = __float2bfloat16(v);
        g_whi[idx] = h;
        g_wlo[idx] = __float2bfloat16(v - __bfloat162float(h));
    }
}

// ---------------- load helpers for main kernel ----------------
__device__ __forceinline__ void load_B(uint32_t sb, int tid, int o0, int j) {
    int ic = j >> 4, k = j & 15;
    uint32_t base = sb + B_OFF + (uint32_t)(j % 3) * BSTG;
    const char* gwhi = (const char*)g_whi;
    const char* gwlo = (const char*)g_wlo;
#pragma unroll
    for (int q = 0; q < 2; q++) {
        int u = q * 256 + tid;
        int o = u >> 2, seg = u & 3;
        size_t g = ((size_t)(k * CO + o0 + o)) * (CI * 2) + (size_t)ic * ICH * 2 + seg * 16;
        uint32_t so = base + o * BSTRIDE + seg * 16;
        cp16(so, gwhi + g);
        cp16(so + B_LO, gwlo + g);
    }
}

// one of 8 parts (18 rows) of the A chunk for channel block ic -> buffer ic&1
__device__ __forceinline__ void load_A_part(uint32_t sb, int tid, int b, int t0,
                                            int ic, int part) {
    if (tid < 72) {
        int row = part * 18 + (tid >> 2);
        if (row < AROWS) {
            int seg = tid & 3;
            size_t g = ((size_t)(b * SPAD + t0 + row)) * (CI * 2)
                     + (size_t)ic * ICH * 2 + seg * 16;
            uint32_t so = sb + (uint32_t)(ic & 1) * ABUF + row * ASTRIDE + seg * 16;
            cp16(so, (const char*)g_xhi + g);
            cp16(so + A_LO, (const char*)g_xlo + g);
        }
    }
}

// ---------------- main HMMA kernel ----------------
__global__ __launch_bounds__(256, 2)
void conv_mma_kernel(float* __restrict__ out) {
    extern __shared__ char smem[];
    const uint32_t sb = s2u(smem);
    const int tid = threadIdx.x;
    const int l = tid & 31, wid = tid >> 5;
    const int wm = wid & 3, wn = wid >> 2;      // 4(m) x 2(n), warp tile 32x64
    const int t0 = blockIdx.x * MT;
    const int b  = blockIdx.y;
    const int o0 = blockIdx.z * NT;

    float acc[2][8][4];
#pragma unroll
    for (int mt = 0; mt < 2; mt++)
#pragma unroll
        for (int n = 0; n < 8; n++)
#pragma unroll
            for (int q = 0; q < 4; q++) acc[mt][n][q] = 0.f;

    const int lm = l & 15;                          // A row within 16
    const int lg = l >> 4;                          // A k-half
    const int bo_row = (l & 7) + ((l >> 4) << 3);   // B o-row within 16
    const int bhalf = (l >> 3) & 1;                 // B k-half

    // ---- prologue: full A(ic=0) + B(0) -> group 0 ; B(1) -> group 1 ----
    {
        const char* gxhi = (const char*)g_xhi;
        const char* gxlo = (const char*)g_xlo;
#pragma unroll
        for (int q = 0; q < 3; q++) {
            int u = q * 256 + tid;
            if (u < AROWS * 4) {
                int row = u >> 2, seg = u & 3;
                size_t g = ((size_t)(b * SPAD + t0 + row)) * (CI * 2) + seg * 16;
                uint32_t so = sb + row * ASTRIDE + seg * 16;
                cp16(so, gxhi + g);
                cp16(so + A_LO, gxlo + g);
            }
        }
        load_B(sb, tid, o0, 0);
        cp_commit();                 // group 0
        load_B(sb, tid, o0, 1);
        cp_commit();                 // group 1
    }

    for (int j = 0; j < NITER; j++) {
        cp_wait1();                  // group j complete (j+1 may pend)
        __syncthreads();             // data j visible; stage (j-1)%3 free

        // prefetch j+2 (B) + folded A part for next ic
        if (j + 2 < NITER) load_B(sb, tid, o0, j + 2);
        {
            int jk = j & 15, jic = j >> 4;
            if (jk >= 5 && jk <= 12 && jic + 1 < NIC)
                load_A_part(sb, tid, b, t0, jic + 1, jk - 5);
        }
        cp_commit();                 // group j+2

        // ---- compute iteration j ----
        const int k = j & 15;
        const uint32_t abase = sb + (uint32_t)((j >> 4) & 1) * ABUF
                             + (uint32_t)(k + wm * 32 + lm) * ASTRIDE + lg * 16;
        const uint32_t bbase = sb + B_OFF + (uint32_t)(j % 3) * BSTG
                             + (uint32_t)(wn * 64 + bo_row) * BSTRIDE + bhalf * 16;
#pragma unroll
        for (int ks = 0; ks < 2; ks++) {
            uint32_t ah[2][4], al[2][4];
#pragma unroll
            for (int mt = 0; mt < 2; mt++) {
                uint32_t a0 = abase + (uint32_t)(mt * 16) * ASTRIDE + ks * 32;
                ldm_x4(ah[mt], a0);
                ldm_x4(al[mt], a0 + A_LO);
            }
#pragma unroll
            for (int p = 0; p < 4; p++) {
                uint32_t bh[4], bl[4];
                uint32_t b0 = bbase + (uint32_t)(p * 16) * BSTRIDE + ks * 32;
                ldm_x4(bh, b0);
                ldm_x4(bl, b0 + B_LO);
#pragma unroll
                for (int half = 0; half < 2; half++) {
                    int n = p * 2 + half;
                    const uint32_t* bhp = &bh[half * 2];
                    const uint32_t* blp = &bl[half * 2];
#pragma unroll
                    for (int mt = 0; mt < 2; mt++) {
                        mma16816(acc[mt][n], ah[mt], bhp);
                        mma16816(acc[mt][n], ah[mt], blp);
                        mma16816(acc[mt][n], al[mt], bhp);
                    }
                }
            }
        }
    }

    // ---- epilogue: direct register -> gmem ----
    const int lr = l >> 2, lc = l & 3;
#pragma unroll
    for (int mt = 0; mt < 2; mt++) {
        int r0 = t0 + wm * 32 + mt * 16 + lr;
        int r1 = r0 + 8;
#pragma unroll
        for (int n = 0; n < 8; n++) {
            int o = o0 + wn * 64 + n * 8 + lc * 2;
            if (r0 < TOUT) {
                float2 v = make_float2(acc[mt][n][0], acc[mt][n][1]);
                *reinterpret_cast<float2*>(out + ((size_t)b * TOUT + r0) * CO + o) = v;
            }
            if (r1 < TOUT) {
                float2 v = make_float2(acc[mt][n][2], acc[mt][n][3]);
                *reinterpret_cast<float2*>(out + ((size_t)b * TOUT + r1) * CO + o) = v;
            }
        }
    }
}

// ---------------- launch ----------------
extern "C" void kernel_launch(void* const* d_in, const int* in_sizes, int n_in,
                              void* d_out, int out_size) {
    const float* x  = (const float*)d_in[0];
    const float* wr = (const float*)d_in[1];
    const float* wi = (const float*)d_in[2];
    const float* ph = (const float*)d_in[3];
    float* out = (float*)d_out;
    (void)in_sizes; (void)n_in; (void)out_size;

    cudaFuncSetAttribute(conv_mma_kernel,
                         cudaFuncAttributeMaxDynamicSharedMemorySize, SMEM_TOTAL);

    prep_kernel<<<XBLOCKS + WBLOCKS, 256>>>(x, wr, wi, ph);

    dim3 grid(SS / MT, NB, CO / NT);   // 16 x 32 x 2 = 1024 CTAs
    conv_mma_kernel<<<grid, 256, SMEM_TOTAL>>>(out);
}

// round 8
// speedup vs baseline: 1.8602x; 1.5250x over previous
#include <cuda_runtime.h>
#include <cuda_fp16.h>
#include <cstdint>

#define NB   32
#define SS   2048
#define SPAD 2064
#define CI   256
#define CO   256
#define KW   16
#define TOUT 2033

#define MT   128           // t rows per CTA
#define NT   128           // o cols per CTA
#define ICH  32            // i-channels per reduction chunk
#define NIC  (CI / ICH)    // 8
#define NITER (NIC * KW)   // 128 flat iterations
#define AROWS 143

#define ASTRIDE 80
#define BSTRIDE 80

#define A_LO   11520                 // 144*80, lo half within an A buffer
#define ABUF   23040                 // one A buffer (hi+lo)
#define B_OFF  46080                 // after 2 A buffers
#define BSTG   10240                 // one B stage (hi only)
#define SMEM_TOTAL (B_OFF + 3 * BSTG)   // 76800

// ---------------- device scratch ----------------
__device__ __half g_xhi[(size_t)NB * SPAD * CI];
__device__ __half g_xlo[(size_t)NB * SPAD * CI];
__device__ __half g_whi[(size_t)KW * CO * CI];   // [k][o][i]

// ---------------- helpers ----------------
__device__ __forceinline__ uint32_t s2u(const void* p) {
    uint32_t a;
    asm("{ .reg .u64 t; cvta.to.shared.u64 t, %1; cvt.u32.u64 %0, t; }"
        : "=r"(a) : "l"(p));
    return a;
}
__device__ __forceinline__ void cp16(uint32_t d, const void* s) {
    asm volatile("cp.async.cg.shared.global [%0], [%1], 16;" :: "r"(d), "l"(s));
}
__device__ __forceinline__ void cp_commit() {
    asm volatile("cp.async.commit_group;" ::: "memory");
}
__device__ __forceinline__ void cp_wait1() {
    asm volatile("cp.async.wait_group 1;" ::: "memory");
}
__device__ __forceinline__ void ldm_x4(uint32_t* r, uint32_t a) {
    asm volatile("ldmatrix.sync.aligned.m8n8.x4.shared.b16 {%0,%1,%2,%3}, [%4];"
                 : "=r"(r[0]), "=r"(r[1]), "=r"(r[2]), "=r"(r[3]) : "r"(a));
}
__device__ __forceinline__ void mma16816(float* c, const uint32_t* a, const uint32_t* b) {
    asm volatile(
        "mma.sync.aligned.m16n8k16.row.col.f32.f16.f16.f32 "
        "{%0,%1,%2,%3}, {%4,%5,%6,%7}, {%8,%9}, {%0,%1,%2,%3};"
        : "+f"(c[0]), "+f"(c[1]), "+f"(c[2]), "+f"(c[3])
        : "r"(a[0]), "r"(a[1]), "r"(a[2]), "r"(a[3]), "r"(b[0]), "r"(b[1]));
}

// ---------------- fused prep kernel ----------------
#define XBLOCKS 16512      // NB*SPAD*CI/4 / 256
#define WBLOCKS 4096       // KW*CO*CI / 256

__global__ void prep_kernel(const float* __restrict__ x,
                            const float* __restrict__ wr,
                            const float* __restrict__ wi,
                            const float* __restrict__ ph) {
    if (blockIdx.x < XBLOCKS) {
        size_t idx4 = (size_t)blockIdx.x * 256 + threadIdx.x;
        size_t idx = idx4 * 4;
        int i = idx & (CI - 1);
        size_t r = idx >> 8;
        int t = (int)(r % SPAD);
        int b = (int)(r / SPAD);
        float4 v = make_float4(0.f, 0.f, 0.f, 0.f);
        if (t < SS)
            v = *reinterpret_cast<const float4*>(x + ((size_t)b * SS + t) * CI + i);
        __half h0 = __float2half(v.x), h1 = __float2half(v.y);
        __half h2 = __float2half(v.z), h3 = __float2half(v.w);
        __half2* hi = reinterpret_cast<__half2*>(g_xhi + idx);
        __half2* lo = reinterpret_cast<__half2*>(g_xlo + idx);
        hi[0] = __half2(h0, h1);
        hi[1] = __half2(h2, h3);
        lo[0] = __half2(__float2half(v.x - __half2float(h0)),
                        __float2half(v.y - __half2float(h1)));
        lo[1] = __half2(__float2half(v.z - __half2float(h2)),
                        __float2half(v.w - __half2float(h3)));
    } else {
        int idx = (blockIdx.x - XBLOCKS) * 256 + threadIdx.x;
        int i = idx & (CI - 1);
        int o = (idx >> 8) & (CO - 1);
        int k = idx >> 16;
        float s, c;
        sincosf(ph[k], &s, &c);
        int widx = (o * CI + i) * KW + k;        // w_real/w_imag are [o][i][k]
        float v = c * wr[widx] - s * wi[widx];
        g_whi[idx] = __float2half(v);
    }
}

// ---------------- load helpers for main kernel ----------------
__device__ __forceinline__ void load_B(uint32_t sb, int tid, int o0, int j) {
    int ic = j >> 4, k = j & 15;
    uint32_t base = sb + B_OFF + (uint32_t)(j % 3) * BSTG;
    const char* gwhi = (const char*)g_whi;
#pragma unroll
    for (int q = 0; q < 2; q++) {
        int u = q * 256 + tid;
        int o = u >> 2, seg = u & 3;
        size_t g = ((size_t)(k * CO + o0 + o)) * (CI * 2) + (size_t)ic * ICH * 2 + seg * 16;
        cp16(base + o * BSTRIDE + seg * 16, gwhi + g);
    }
}

// one of 8 parts (18 rows) of the A chunk for channel block ic -> buffer ic&1
__device__ __forceinline__ void load_A_part(uint32_t sb, int tid, int b, int t0,
                                            int ic, int part) {
    if (tid < 72) {
        int row = part * 18 + (tid >> 2);
        if (row < AROWS) {
            int seg = tid & 3;
            size_t g = ((size_t)(b * SPAD + t0 + row)) * (CI * 2)
                     + (size_t)ic * ICH * 2 + seg * 16;
            uint32_t so = sb + (uint32_t)(ic & 1) * ABUF + row * ASTRIDE + seg * 16;
            cp16(so, (const char*)g_xhi + g);
            cp16(so + A_LO, (const char*)g_xlo + g);
        }
    }
}

// ---------------- main HMMA kernel ----------------
__global__ __launch_bounds__(256, 2)
void conv_mma_kernel(float* __restrict__ out) {
    extern __shared__ char smem[];
    const uint32_t sb = s2u(smem);
    const int tid = threadIdx.x;
    const int l = tid & 31, wid = tid >> 5;
    const int wm = wid & 3, wn = wid >> 2;      // 4(m) x 2(n), warp tile 32x64
    const int t0 = blockIdx.x * MT;
    const int b  = blockIdx.y;
    const int o0 = blockIdx.z * NT;

    float acc[2][8][4];
#pragma unroll
    for (int mt = 0; mt < 2; mt++)
#pragma unroll
        for (int n = 0; n < 8; n++)
#pragma unroll
            for (int q = 0; q < 4; q++) acc[mt][n][q] = 0.f;

    const int lm = l & 15;                          // A row within 16
    const int lg = l >> 4;                          // A k-half
    const int bo_row = (l & 7) + ((l >> 4) << 3);   // B o-row within 16
    const int bhalf = (l >> 3) & 1;                 // B k-half

    // ---- prologue: full A(ic=0) + B(0) -> group 0 ; B(1) -> group 1 ----
    {
        const char* gxhi = (const char*)g_xhi;
        const char* gxlo = (const char*)g_xlo;
#pragma unroll
        for (int q = 0; q < 3; q++) {
            int u = q * 256 + tid;
            if (u < AROWS * 4) {
                int row = u >> 2, seg = u & 3;
                size_t g = ((size_t)(b * SPAD + t0 + row)) * (CI * 2) + seg * 16;
                uint32_t so = sb + row * ASTRIDE + seg * 16;
                cp16(so, gxhi + g);
                cp16(so + A_LO, gxlo + g);
            }
        }
        load_B(sb, tid, o0, 0);
        cp_commit();                 // group 0
        load_B(sb, tid, o0, 1);
        cp_commit();                 // group 1
    }

    for (int j = 0; j < NITER; j++) {
        cp_wait1();                  // group j complete (j+1 may pend)
        __syncthreads();             // data j visible; stage (j-1)%3 free

        // prefetch j+2 (B) + folded A part for next ic
        if (j + 2 < NITER) load_B(sb, tid, o0, j + 2);
        {
            int jk = j & 15, jic = j >> 4;
            if (jk >= 5 && jk <= 12 && jic + 1 < NIC)
                load_A_part(sb, tid, b, t0, jic + 1, jk - 5);
        }
        cp_commit();                 // group j+2

        // ---- compute iteration j ----
        const int k = j & 15;
        const uint32_t abase = sb + (uint32_t)((j >> 4) & 1) * ABUF
                             + (uint32_t)(k + wm * 32 + lm) * ASTRIDE + lg * 16;
        const uint32_t bbase = sb + B_OFF + (uint32_t)(j % 3) * BSTG
                             + (uint32_t)(wn * 64 + bo_row) * BSTRIDE + bhalf * 16;
#pragma unroll
        for (int ks = 0; ks < 2; ks++) {
            uint32_t ah[2][4], al[2][4];
#pragma unroll
            for (int mt = 0; mt < 2; mt++) {
                uint32_t a0 = abase + (uint32_t)(mt * 16) * ASTRIDE + ks * 32;
                ldm_x4(ah[mt], a0);
                ldm_x4(al[mt], a0 + A_LO);
            }
#pragma unroll
            for (int p = 0; p < 4; p++) {
                uint32_t bh[4];
                uint32_t b0 = bbase + (uint32_t)(p * 16) * BSTRIDE + ks * 32;
                ldm_x4(bh, b0);
#pragma unroll
                for (int half = 0; half < 2; half++) {
                    int n = p * 2 + half;
                    const uint32_t* bhp = &bh[half * 2];
#pragma unroll
                    for (int mt = 0; mt < 2; mt++) {
                        mma16816(acc[mt][n], ah[mt], bhp);
                        mma16816(acc[mt][n], al[mt], bhp);
                    }
                }
            }
        }
    }

    // ---- epilogue: direct register -> gmem ----
    const int lr = l >> 2, lc = l & 3;
#pragma unroll
    for (int mt = 0; mt < 2; mt++) {
        int r0 = t0 + wm * 32 + mt * 16 + lr;
        int r1 = r0 + 8;
#pragma unroll
        for (int n = 0; n < 8; n++) {
            int o = o0 + wn * 64 + n * 8 + lc * 2;
            if (r0 < TOUT) {
                float2 v = make_float2(acc[mt][n][0], acc[mt][n][1]);
                *reinterpret_cast<float2*>(out + ((size_t)b * TOUT + r0) * CO + o) = v;
            }
            if (r1 < TOUT) {
                float2 v = make_float2(acc[mt][n][2], acc[mt][n][3]);
                *reinterpret_cast<float2*>(out + ((size_t)b * TOUT + r1) * CO + o) = v;
            }
        }
    }
}

// ---------------- launch ----------------
extern "C" void kernel_launch(void* const* d_in, const int* in_sizes, int n_in,
                              void* d_out, int out_size) {
    const float* x  = (const float*)d_in[0];
    const float* wr = (const float*)d_in[1];
    const float* wi = (const float*)d_in[2];
    const float* ph = (const float*)d_in[3];
    float* out = (float*)d_out;
    (void)in_sizes; (void)n_in; (void)out_size;

    cudaFuncSetAttribute(conv_mma_kernel,
                         cudaFuncAttributeMaxDynamicSharedMemorySize, SMEM_TOTAL);

    prep_kernel<<<XBLOCKS + WBLOCKS, 256>>>(x, wr, wi, ph);

    dim3 grid(SS / MT, NB, CO / NT);   // 16 x 32 x 2 = 1024 CTAs
    conv_mma_kernel<<<grid, 256, SMEM_TOTAL>>>(out);
}

// round 9
// speedup vs baseline: 3.0541x; 1.6418x over previous
#include <cuda_runtime.h>
#include <cuda_fp16.h>
#include <cstdint>

#define NB   32
#define SS   2048
#define SPAD 2064
#define CI   256
#define CO   256
#define KW   16
#define TOUT 2033

#define MT   128           // t rows per CTA
#define NT   128           // o cols per CTA
#define ICH  32            // i-channels per reduction chunk
#define NIC  (CI / ICH)    // 8
#define NITER (NIC * KW)   // 128 flat iterations
#define AROWS 143

#define ASTRIDE 80
#define BSTRIDE 80

#define ABUF   11520                 // one A buffer (hi only), 144*80
#define B_OFF  23040                 // after 2 A buffers
#define BSTG   10240                 // one B stage
#define SMEM_TOTAL (B_OFF + 3 * BSTG)   // 53760

// ---------------- device scratch ----------------
__device__ __half g_xhi[(size_t)NB * SPAD * CI];
__device__ __half g_whi[(size_t)KW * CO * CI];   // [k][o][i]

// ---------------- helpers ----------------
__device__ __forceinline__ uint32_t s2u(const void* p) {
    uint32_t a;
    asm("{ .reg .u64 t; cvta.to.shared.u64 t, %1; cvt.u32.u64 %0, t; }"
        : "=r"(a) : "l"(p));
    return a;
}
__device__ __forceinline__ void cp16(uint32_t d, const void* s) {
    asm volatile("cp.async.cg.shared.global [%0], [%1], 16;" :: "r"(d), "l"(s));
}
__device__ __forceinline__ void cp_commit() {
    asm volatile("cp.async.commit_group;" ::: "memory");
}
__device__ __forceinline__ void cp_wait1() {
    asm volatile("cp.async.wait_group 1;" ::: "memory");
}
__device__ __forceinline__ void ldm_x4(uint32_t* r, uint32_t a) {
    asm volatile("ldmatrix.sync.aligned.m8n8.x4.shared.b16 {%0,%1,%2,%3}, [%4];"
                 : "=r"(r[0]), "=r"(r[1]), "=r"(r[2]), "=r"(r[3]) : "r"(a));
}
__device__ __forceinline__ void mma16816(float* c, const uint32_t* a, const uint32_t* b) {
    asm volatile(
        "mma.sync.aligned.m16n8k16.row.col.f32.f16.f16.f32 "
        "{%0,%1,%2,%3}, {%4,%5,%6,%7}, {%8,%9}, {%0,%1,%2,%3};"
        : "+f"(c[0]), "+f"(c[1]), "+f"(c[2]), "+f"(c[3])
        : "r"(a[0]), "r"(a[1]), "r"(a[2]), "r"(a[3]), "r"(b[0]), "r"(b[1]));
}

// ---------------- fused prep kernel ----------------
#define XBLOCKS 16512      // NB*SPAD*CI/4 / 256
#define WBLOCKS 4096       // KW*CO*CI / 256

__global__ void prep_kernel(const float* __restrict__ x,
                            const float* __restrict__ wr,
                            const float* __restrict__ wi,
                            const float* __restrict__ ph) {
    if (blockIdx.x < XBLOCKS) {
        size_t idx4 = (size_t)blockIdx.x * 256 + threadIdx.x;
        size_t idx = idx4 * 4;
        int i = idx & (CI - 1);
        size_t r = idx >> 8;
        int t = (int)(r % SPAD);
        int b = (int)(r / SPAD);
        float4 v = make_float4(0.f, 0.f, 0.f, 0.f);
        if (t < SS)
            v = *reinterpret_cast<const float4*>(x + ((size_t)b * SS + t) * CI + i);
        __half2* hi = reinterpret_cast<__half2*>(g_xhi + idx);
        hi[0] = __half2(__float2half(v.x), __float2half(v.y));
        hi[1] = __half2(__float2half(v.z), __float2half(v.w));
    } else {
        int idx = (blockIdx.x - XBLOCKS) * 256 + threadIdx.x;
        int i = idx & (CI - 1);
        int o = (idx >> 8) & (CO - 1);
        int k = idx >> 16;
        float s, c;
        sincosf(ph[k], &s, &c);
        int widx = (o * CI + i) * KW + k;        // w_real/w_imag are [o][i][k]
        float v = c * wr[widx] - s * wi[widx];
        g_whi[idx] = __float2half(v);
    }
}

// ---------------- load helpers for main kernel ----------------
__device__ __forceinline__ void load_B(uint32_t sb, int tid, int o0, int j) {
    int ic = j >> 4, k = j & 15;
    uint32_t base = sb + B_OFF + (uint32_t)(j % 3) * BSTG;
    const char* gwhi = (const char*)g_whi;
#pragma unroll
    for (int q = 0; q < 2; q++) {
        int u = q * 256 + tid;
        int o = u >> 2, seg = u & 3;
        size_t g = ((size_t)(k * CO + o0 + o)) * (CI * 2) + (size_t)ic * ICH * 2 + seg * 16;
        cp16(base + o * BSTRIDE + seg * 16, gwhi + g);
    }
}

// one of 8 parts (18 rows) of the A chunk for channel block ic -> buffer ic&1
__device__ __forceinline__ void load_A_part(uint32_t sb, int tid, int b, int t0,
                                            int ic, int part) {
    if (tid < 72) {
        int row = part * 18 + (tid >> 2);
        if (row < AROWS) {
            int seg = tid & 3;
            size_t g = ((size_t)(b * SPAD + t0 + row)) * (CI * 2)
                     + (size_t)ic * ICH * 2 + seg * 16;
            uint32_t so = sb + (uint32_t)(ic & 1) * ABUF + row * ASTRIDE + seg * 16;
            cp16(so, (const char*)g_xhi + g);
        }
    }
}

// ---------------- main HMMA kernel ----------------
__global__ __launch_bounds__(256, 2)
void conv_mma_kernel(float* __restrict__ out) {
    extern __shared__ char smem[];
    const uint32_t sb = s2u(smem);
    const int tid = threadIdx.x;
    const int l = tid & 31, wid = tid >> 5;
    const int wm = wid & 3, wn = wid >> 2;      // 4(m) x 2(n), warp tile 32x64
    const int t0 = blockIdx.x * MT;
    const int b  = blockIdx.y;
    const int o0 = blockIdx.z * NT;

    float acc[2][8][4];
#pragma unroll
    for (int mt = 0; mt < 2; mt++)
#pragma unroll
        for (int n = 0; n < 8; n++)
#pragma unroll
            for (int q = 0; q < 4; q++) acc[mt][n][q] = 0.f;

    const int lm = l & 15;                          // A row within 16
    const int lg = l >> 4;                          // A k-half
    const int bo_row = (l & 7) + ((l >> 4) << 3);   // B o-row within 16
    const int bhalf = (l >> 3) & 1;                 // B k-half

    // ---- prologue: full A(ic=0) + B(0) -> group 0 ; B(1) -> group 1 ----
    {
        const char* gxhi = (const char*)g_xhi;
#pragma unroll
        for (int q = 0; q < 3; q++) {
            int u = q * 256 + tid;
            if (u < AROWS * 4) {
                int row = u >> 2, seg = u & 3;
                size_t g = ((size_t)(b * SPAD + t0 + row)) * (CI * 2) + seg * 16;
                cp16(sb + row * ASTRIDE + seg * 16, gxhi + g);
            }
        }
        load_B(sb, tid, o0, 0);
        cp_commit();                 // group 0
        load_B(sb, tid, o0, 1);
        cp_commit();                 // group 1
    }

    for (int j = 0; j < NITER; j++) {
        cp_wait1();                  // group j complete (j+1 may pend)
        __syncthreads();             // data j visible; stage (j-1)%3 free

        // prefetch j+2 (B) + folded A part for next ic
        if (j + 2 < NITER) load_B(sb, tid, o0, j + 2);
        {
            int jk = j & 15, jic = j >> 4;
            if (jk >= 5 && jk <= 12 && jic + 1 < NIC)
                load_A_part(sb, tid, b, t0, jic + 1, jk - 5);
        }
        cp_commit();                 // group j+2

        // ---- compute iteration j ----
        const int k = j & 15;
        const uint32_t abase = sb + (uint32_t)((j >> 4) & 1) * ABUF
                             + (uint32_t)(k + wm * 32 + lm) * ASTRIDE + lg * 16;
        const uint32_t bbase = sb + B_OFF + (uint32_t)(j % 3) * BSTG
                             + (uint32_t)(wn * 64 + bo_row) * BSTRIDE + bhalf * 16;
#pragma unroll
        for (int ks = 0; ks < 2; ks++) {
            uint32_t ah[2][4];
#pragma unroll
            for (int mt = 0; mt < 2; mt++)
                ldm_x4(ah[mt], abase + (uint32_t)(mt * 16) * ASTRIDE + ks * 32);
#pragma unroll
            for (int p = 0; p < 4; p++) {
                uint32_t bh[4];
                ldm_x4(bh, bbase + (uint32_t)(p * 16) * BSTRIDE + ks * 32);
#pragma unroll
                for (int half = 0; half < 2; half++) {
                    int n = p * 2 + half;
                    const uint32_t* bhp = &bh[half * 2];
#pragma unroll
                    for (int mt = 0; mt < 2; mt++)
                        mma16816(acc[mt][n], ah[mt], bhp);
                }
            }
        }
    }

    // ---- epilogue: direct register -> gmem ----
    const int lr = l >> 2, lc = l & 3;
#pragma unroll
    for (int mt = 0; mt < 2; mt++) {
        int r0 = t0 + wm * 32 + mt * 16 + lr;
        int r1 = r0 + 8;
#pragma unroll
        for (int n = 0; n < 8; n++) {
            int o = o0 + wn * 64 + n * 8 + lc * 2;
            if (r0 < TOUT) {
                float2 v = make_float2(acc[mt][n][0], acc[mt][n][1]);
                *reinterpret_cast<float2*>(out + ((size_t)b * TOUT + r0) * CO + o) = v;
            }
            if (r1 < TOUT) {
                float2 v = make_float2(acc[mt][n][2], acc[mt][n][3]);
                *reinterpret_cast<float2*>(out + ((size_t)b * TOUT + r1) * CO + o) = v;
            }
        }
    }
}

// ---------------- launch ----------------
extern "C" void kernel_launch(void* const* d_in, const int* in_sizes, int n_in,
                              void* d_out, int out_size) {
    const float* x  = (const float*)d_in[0];
    const float* wr = (const float*)d_in[1];
    const float* wi = (const float*)d_in[2];
    const float* ph = (const float*)d_in[3];
    float* out = (float*)d_out;
    (void)in_sizes; (void)n_in; (void)out_size;

    cudaFuncSetAttribute(conv_mma_kernel,
                         cudaFuncAttributeMaxDynamicSharedMemorySize, SMEM_TOTAL);

    prep_kernel<<<XBLOCKS + WBLOCKS, 256>>>(x, wr, wi, ph);

    dim3 grid(SS / MT, NB, CO / NT);   // 16 x 32 x 2 = 1024 CTAs
    conv_mma_kernel<<<grid, 256, SMEM_TOTAL>>>(out);
}

// round 10
// speedup vs baseline: 3.2476x; 1.0633x over previous
#include <cuda_runtime.h>
#include <cuda_fp16.h>
#include <cstdint>

#define NB   32
#define SS   2048
#define SPAD 2064
#define CI   256
#define CO   256
#define KW   16
#define TOUT 2033

#define MT   128           // t rows per CTA
#define NT   128           // o cols per CTA
#define ICH  64            // i-channels per reduction chunk
#define NIC  (CI / ICH)    // 4
#define NITER (NIC * KW)   // 64 flat iterations
#define AROWS 143

#define ASTRIDE 144        // 64 halves = 128B data + 16B pad
#define BSTRIDE 144

#define ABUF   20736                 // one A buffer: 144 rows * 144B
#define B_OFF  41472                 // after 2 A buffers
#define BSTG   18432                 // one B stage: 128 rows * 144B
#define SMEM_TOTAL (B_OFF + 3 * BSTG)   // 96768

// ---------------- device scratch ----------------
__device__ __half g_xhi[(size_t)NB * SPAD * CI];
__device__ __half g_whi[(size_t)KW * CO * CI];   // [k][o][i]

// ---------------- helpers ----------------
__device__ __forceinline__ uint32_t s2u(const void* p) {
    uint32_t a;
    asm("{ .reg .u64 t; cvta.to.shared.u64 t, %1; cvt.u32.u64 %0, t; }"
        : "=r"(a) : "l"(p));
    return a;
}
__device__ __forceinline__ void cp16(uint32_t d, const void* s) {
    asm volatile("cp.async.cg.shared.global [%0], [%1], 16;" :: "r"(d), "l"(s));
}
__device__ __forceinline__ void cp_commit() {
    asm volatile("cp.async.commit_group;" ::: "memory");
}
__device__ __forceinline__ void cp_wait1() {
    asm volatile("cp.async.wait_group 1;" ::: "memory");
}
__device__ __forceinline__ void ldm_x4(uint32_t* r, uint32_t a) {
    asm volatile("ldmatrix.sync.aligned.m8n8.x4.shared.b16 {%0,%1,%2,%3}, [%4];"
                 : "=r"(r[0]), "=r"(r[1]), "=r"(r[2]), "=r"(r[3]) : "r"(a));
}
__device__ __forceinline__ void mma16816(float* c, const uint32_t* a, const uint32_t* b) {
    asm volatile(
        "mma.sync.aligned.m16n8k16.row.col.f32.f16.f16.f32 "
        "{%0,%1,%2,%3}, {%4,%5,%6,%7}, {%8,%9}, {%0,%1,%2,%3};"
        : "+f"(c[0]), "+f"(c[1]), "+f"(c[2]), "+f"(c[3])
        : "r"(a[0]), "r"(a[1]), "r"(a[2]), "r"(a[3]), "r"(b[0]), "r"(b[1]));
}

// ---------------- fused prep kernel ----------------
#define XBLOCKS 16512      // NB*SPAD*CI/4 / 256
#define WBLOCKS 4096       // KW*CO*CI / 256

__global__ void prep_kernel(const float* __restrict__ x,
                            const float* __restrict__ wr,
                            const float* __restrict__ wi,
                            const float* __restrict__ ph) {
    if (blockIdx.x < XBLOCKS) {
        size_t idx4 = (size_t)blockIdx.x * 256 + threadIdx.x;
        size_t idx = idx4 * 4;
        int i = idx & (CI - 1);
        size_t r = idx >> 8;
        int t = (int)(r % SPAD);
        int b = (int)(r / SPAD);
        float4 v = make_float4(0.f, 0.f, 0.f, 0.f);
        if (t < SS)
            v = *reinterpret_cast<const float4*>(x + ((size_t)b * SS + t) * CI + i);
        __half2* hi = reinterpret_cast<__half2*>(g_xhi + idx);
        hi[0] = __half2(__float2half(v.x), __float2half(v.y));
        hi[1] = __half2(__float2half(v.z), __float2half(v.w));
    } else {
        int idx = (blockIdx.x - XBLOCKS) * 256 + threadIdx.x;
        int i = idx & (CI - 1);
        int o = (idx >> 8) & (CO - 1);
        int k = idx >> 16;
        float s, c;
        sincosf(ph[k], &s, &c);
        int widx = (o * CI + i) * KW + k;        // w_real/w_imag are [o][i][k]
        float v = c * wr[widx] - s * wi[widx];
        g_whi[idx] = __float2half(v);
    }
}

// ---------------- load helpers for main kernel ----------------
// B tile for flat iter j: 128 o-rows x 64 i = 1024 cp16 (4 per thread)
__device__ __forceinline__ void load_B(uint32_t sb, int tid, int o0, int j) {
    int ic = j >> 4, k = j & 15;
    uint32_t base = sb + B_OFF + (uint32_t)(j % 3) * BSTG;
    const char* gwhi = (const char*)g_whi;
#pragma unroll
    for (int q = 0; q < 4; q++) {
        int u = q * 256 + tid;
        int o = u >> 3, seg = u & 7;
        size_t g = ((size_t)(k * CO + o0 + o)) * (CI * 2) + (size_t)ic * ICH * 2 + seg * 16;
        cp16(base + o * BSTRIDE + seg * 16, gwhi + g);
    }
}

// one of 8 parts (18 rows x 8 segs = 144 cp16) of next A chunk -> buffer ic&1
__device__ __forceinline__ void load_A_part(uint32_t sb, int tid, int b, int t0,
                                            int ic, int part) {
    if (tid < 144) {
        int row = part * 18 + (tid >> 3);
        if (row < AROWS) {
            int seg = tid & 7;
            size_t g = ((size_t)(b * SPAD + t0 + row)) * (CI * 2)
                     + (size_t)ic * ICH * 2 + seg * 16;
            cp16(sb + (uint32_t)(ic & 1) * ABUF + row * ASTRIDE + seg * 16,
                 (const char*)g_xhi + g);
        }
    }
}

// ---------------- main HMMA kernel ----------------
__global__ __launch_bounds__(256, 2)
void conv_mma_kernel(float* __restrict__ out) {
    extern __shared__ char smem[];
    const uint32_t sb = s2u(smem);
    const int tid = threadIdx.x;
    const int l = tid & 31, wid = tid >> 5;
    const int wm = wid & 3, wn = wid >> 2;      // 4(m) x 2(n), warp tile 32x64
    const int t0 = blockIdx.x * MT;
    const int b  = blockIdx.y;
    const int o0 = blockIdx.z * NT;

    float acc[2][8][4];
#pragma unroll
    for (int mt = 0; mt < 2; mt++)
#pragma unroll
        for (int n = 0; n < 8; n++)
#pragma unroll
            for (int q = 0; q < 4; q++) acc[mt][n][q] = 0.f;

    const int lm = l & 15;                          // A row within 16
    const int lg = l >> 4;                          // A k-half
    const int bo_row = (l & 7) + ((l >> 4) << 3);   // B o-row within 16
    const int bhalf = (l >> 3) & 1;                 // B k-half

    // ---- prologue: full A(ic=0) + B(0) -> group 0 ; B(1) -> group 1 ----
    {
        const char* gxhi = (const char*)g_xhi;
#pragma unroll
        for (int q = 0; q < 5; q++) {
            int u = q * 256 + tid;
            if (u < AROWS * 8) {
                int row = u >> 3, seg = u & 7;
                size_t g = ((size_t)(b * SPAD + t0 + row)) * (CI * 2) + seg * 16;
                cp16(sb + row * ASTRIDE + seg * 16, gxhi + g);
            }
        }
        load_B(sb, tid, o0, 0);
        cp_commit();                 // group 0
        load_B(sb, tid, o0, 1);
        cp_commit();                 // group 1
    }

    for (int j = 0; j < NITER; j++) {
        cp_wait1();                  // group j complete (j+1 may pend)
        __syncthreads();             // data j visible; stage (j-1)%3 free

        // prefetch j+2 (B) + folded A part for next ic
        if (j + 2 < NITER) load_B(sb, tid, o0, j + 2);
        {
            int jk = j & 15, jic = j >> 4;
            if (jk >= 5 && jk <= 12 && jic + 1 < NIC)
                load_A_part(sb, tid, b, t0, jic + 1, jk - 5);
        }
        cp_commit();                 // group j+2

        // ---- compute iteration j (K = 64 channels = 4 k-steps) ----
        const int k = j & 15;
        const uint32_t abase = sb + (uint32_t)((j >> 4) & 1) * ABUF
                             + (uint32_t)(k + wm * 32 + lm) * ASTRIDE + lg * 16;
        const uint32_t bbase = sb + B_OFF + (uint32_t)(j % 3) * BSTG
                             + (uint32_t)(wn * 64 + bo_row) * BSTRIDE + bhalf * 16;
#pragma unroll
        for (int ks = 0; ks < 4; ks++) {
            uint32_t ah[2][4];
#pragma unroll
            for (int mt = 0; mt < 2; mt++)
                ldm_x4(ah[mt], abase + (uint32_t)(mt * 16) * ASTRIDE + ks * 32);
#pragma unroll
            for (int p = 0; p < 4; p++) {
                uint32_t bh[4];
                ldm_x4(bh, bbase + (uint32_t)(p * 16) * BSTRIDE + ks * 32);
#pragma unroll
                for (int half = 0; half < 2; half++) {
                    int n = p * 2 + half;
                    const uint32_t* bhp = &bh[half * 2];
#pragma unroll
                    for (int mt = 0; mt < 2; mt++)
                        mma16816(acc[mt][n], ah[mt], bhp);
                }
            }
        }
    }

    // ---- epilogue: direct register -> gmem ----
    const int lr = l >> 2, lc = l & 3;
#pragma unroll
    for (int mt = 0; mt < 2; mt++) {
        int r0 = t0 + wm * 32 + mt * 16 + lr;
        int r1 = r0 + 8;
#pragma unroll
        for (int n = 0; n < 8; n++) {
            int o = o0 + wn * 64 + n * 8 + lc * 2;
            if (r0 < TOUT) {
                float2 v = make_float2(acc[mt][n][0], acc[mt][n][1]);
                *reinterpret_cast<float2*>(out + ((size_t)b * TOUT + r0) * CO + o) = v;
            }
            if (r1 < TOUT) {
                float2 v = make_float2(acc[mt][n][2], acc[mt][n][3]);
                *reinterpret_cast<float2*>(out + ((size_t)b * TOUT + r1) * CO + o) = v;
            }
        }
    }
}

// ---------------- launch ----------------
extern "C" void kernel_launch(void* const* d_in, const int* in_sizes, int n_in,
                              void* d_out, int out_size) {
    const float* x  = (const float*)d_in[0];
    const float* wr = (const float*)d_in[1];
    const float* wi = (const float*)d_in[2];
    const float* ph = (const float*)d_in[3];
    float* out = (float*)d_out;
    (void)in_sizes; (void)n_in; (void)out_size;

    cudaFuncSetAttribute(conv_mma_kernel,
                         cudaFuncAttributeMaxDynamicSharedMemorySize, SMEM_TOTAL);

    prep_kernel<<<XBLOCKS + WBLOCKS, 256>>>(x, wr, wi, ph);

    dim3 grid(SS / MT, NB, CO / NT);   // 16 x 32 x 2 = 1024 CTAs
    conv_mma_kernel<<<grid, 256, SMEM_TOTAL>>>(out);
}

// round 11
// speedup vs baseline: 3.5931x; 1.1064x over previous
#include <cuda_runtime.h>
#include <cuda_fp16.h>
#include <cstdint>

#define NB   32
#define SS   2048
#define SPAD 2064
#define CI   256
#define CO   256
#define KW   16
#define TOUT 2033

#define MT   128
#define NT   128
#define ICH  64
#define NIC  (CI / ICH)    // 4
#define NITER (NIC * KW)   // 64
#define AROWS 143

#define ABUF   18432                 // 144 rows * 128B (bulk copies 143*128=18304)
#define A_OFF  1024
#define B_OFF  (A_OFF + 2 * ABUF)    // 37888
#define BSTG   16384                 // 128 rows * 128B
#define SMEM_TOTAL (B_OFF + 3 * BSTG)   // 87040

#define A_BYTES (AROWS * 128)        // 18304
#define B_BYTES (128 * 128)          // 16384

// mbarriers in smem: B stages at +0,+8,+16 ; A bufs at +24,+32
#define MB_B(s) (sb + 8u * (uint32_t)(s))
#define MB_A(p) (sb + 24u + 8u * (uint32_t)(p))

// ---------------- device scratch (pre-swizzled, tile-contiguous) ----------------
__device__ __half g_xt[(size_t)NB * NIC * SPAD * 64];   // [b][ic][t][row 128B, SW128]
__device__ __half g_wt[(size_t)KW * NIC * CO * 64];     // [k][ic][o][row 128B, SW128]

// ---------------- helpers ----------------
__device__ __forceinline__ uint32_t s2u(const void* p) {
    uint32_t a;
    asm("{ .reg .u64 t; cvta.to.shared.u64 t, %1; cvt.u32.u64 %0, t; }"
        : "=r"(a) : "l"(p));
    return a;
}
__device__ __forceinline__ void mbar_init(uint32_t a) {
    asm volatile("mbarrier.init.shared.b64 [%0], 1;" :: "r"(a) : "memory");
}
__device__ __forceinline__ void mbar_expect(uint32_t a, uint32_t bytes) {
    asm volatile("mbarrier.arrive.expect_tx.shared.b64 _, [%0], %1;"
                 :: "r"(a), "r"(bytes) : "memory");
}
__device__ __forceinline__ void bulk_g2s(uint32_t dst, const void* src,
                                         uint32_t bytes, uint32_t mbar) {
    asm volatile(
        "cp.async.bulk.shared::cluster.global.mbarrier::complete_tx::bytes "
        "[%0], [%1], %2, [%3];"
        :: "r"(dst), "l"(src), "r"(bytes), "r"(mbar) : "memory");
}
__device__ __forceinline__ void mbar_wait(uint32_t a, uint32_t parity) {
    asm volatile(
        "{\n\t.reg .pred P;\n\t"
        "WL_%=:\n\t"
        "mbarrier.try_wait.parity.acquire.cta.shared::cta.b64 P, [%0], %1, 0x989680;\n\t"
        "@P bra.uni WD_%=;\n\t"
        "bra.uni WL_%=;\n\t"
        "WD_%=:\n\t}"
        :: "r"(a), "r"(parity) : "memory");
}
__device__ __forceinline__ void ldm_x4(uint32_t* r, uint32_t a) {
    asm volatile("ldmatrix.sync.aligned.m8n8.x4.shared.b16 {%0,%1,%2,%3}, [%4];"
                 : "=r"(r[0]), "=r"(r[1]), "=r"(r[2]), "=r"(r[3]) : "r"(a));
}
__device__ __forceinline__ void mma16816(float* c, const uint32_t* a, const uint32_t* b) {
    asm volatile(
        "mma.sync.aligned.m16n8k16.row.col.f32.f16.f16.f32 "
        "{%0,%1,%2,%3}, {%4,%5,%6,%7}, {%8,%9}, {%0,%1,%2,%3};"
        : "+f"(c[0]), "+f"(c[1]), "+f"(c[2]), "+f"(c[3])
        : "r"(a[0]), "r"(a[1]), "r"(a[2]), "r"(a[3]), "r"(b[0]), "r"(b[1]));
}

// ---------------- fused prep kernel (writes pre-swizzled layouts) ----------------
#define XBLOCKS 16512      // NB*SPAD*CI/4 / 256
#define WBLOCKS 4096       // KW*CO*CI / 256

__global__ void prep_kernel(const float* __restrict__ x,
                            const float* __restrict__ wr,
                            const float* __restrict__ wi,
                            const float* __restrict__ ph) {
    if (blockIdx.x < XBLOCKS) {
        size_t idx4 = (size_t)blockIdx.x * 256 + threadIdx.x;
        size_t idx = idx4 * 4;
        int i = idx & (CI - 1);
        size_t r = idx >> 8;
        int t = (int)(r % SPAD);
        int b = (int)(r / SPAD);
        float4 v = make_float4(0.f, 0.f, 0.f, 0.f);
        if (t < SS)
            v = *reinterpret_cast<const float4*>(x + ((size_t)b * SS + t) * CI + i);
        __half2 h01(__float2half(v.x), __float2half(v.y));
        __half2 h23(__float2half(v.z), __float2half(v.w));
        int ic = i >> 6;
        int cb = (i & 63) * 2;                       // byte col within 128B row
        size_t dst = ((size_t)(b * NIC + ic) * SPAD + t) * 128
                   + (uint32_t)(cb ^ ((t & 7) << 4));
        uint2 u;
        u.x = *reinterpret_cast<uint32_t*>(&h01);
        u.y = *reinterpret_cast<uint32_t*>(&h23);
        *reinterpret_cast<uint2*>(reinterpret_cast<char*>(g_xt) + dst) = u;
    } else {
        int idx = (blockIdx.x - XBLOCKS) * 256 + threadIdx.x;
        int i = idx & (CI - 1);
        int o = (idx >> 8) & (CO - 1);
        int k = idx >> 16;
        float s, c;
        sincosf(ph[k], &s, &c);
        int widx = (o * CI + i) * KW + k;            // w_real/w_imag are [o][i][k]
        float v = c * wr[widx] - s * wi[widx];
        int ic = i >> 6;
        int cb = (i & 63) * 2;
        size_t dst = ((size_t)(k * NIC + ic) * CO + o) * 128
                   + (uint32_t)(cb ^ ((o & 7) << 4));
        *reinterpret_cast<__half*>(reinterpret_cast<char*>(g_wt) + dst) = __float2half(v);
    }
}

// ---------------- main HMMA kernel ----------------
__global__ __launch_bounds__(256, 2)
void conv_mma_kernel(float* __restrict__ out) {
    extern __shared__ char smem[];
    const uint32_t sb = s2u(smem);
    const int tid = threadIdx.x;
    const int l = tid & 31, wid = tid >> 5;
    const int wm = wid & 3, wn = wid >> 2;      // 4(m) x 2(n), warp tile 32x64
    const int t0 = blockIdx.x * MT;
    const int b  = blockIdx.y;
    const int o0 = blockIdx.z * NT;

    const char* gxt = (const char*)g_xt;
    const char* gwt = (const char*)g_wt;

    float acc[2][8][4];
#pragma unroll
    for (int mt = 0; mt < 2; mt++)
#pragma unroll
        for (int n = 0; n < 8; n++)
#pragma unroll
            for (int q = 0; q < 4; q++) acc[mt][n][q] = 0.f;

    const int lm = l & 15;                          // A row within 16
    const int lg = l >> 4;                          // A k-half
    const int bo_row = (l & 7) + ((l >> 4) << 3);   // B o-row within 16
    const int bhalf = (l >> 3) & 1;                 // B k-half
    const uint32_t rxb = (uint32_t)(l & 7) << 4;    // B swizzle term (row&7)<<4

    // ---- prologue ----
    if (tid == 0) {
        mbar_init(MB_B(0)); mbar_init(MB_B(1)); mbar_init(MB_B(2));
        mbar_init(MB_A(0)); mbar_init(MB_A(1));
    }
    __syncthreads();
    if (tid == 0) {
        // A chunk ic=0 -> buf 0
        mbar_expect(MB_A(0), A_BYTES);
        bulk_g2s(sb + A_OFF,
                 gxt + ((size_t)(b * NIC + 0) * SPAD + t0) * 128, A_BYTES, MB_A(0));
        // B tiles j=0,1 -> stages 0,1
#pragma unroll
        for (int j = 0; j < 2; j++) {
            int ic = j >> 4, k = j & 15;
            mbar_expect(MB_B(j), B_BYTES);
            bulk_g2s(sb + B_OFF + (uint32_t)j * BSTG,
                     gwt + ((size_t)(k * NIC + ic) * CO + o0) * 128, B_BYTES, MB_B(j));
        }
    }

    for (int j = 0; j < NITER; j++) {
        const int ic = j >> 4, k = j & 15;
        if ((j & 15) == 0) mbar_wait(MB_A(ic & 1), (ic >> 1) & 1);
        mbar_wait(MB_B(j % 3), (j / 3) & 1);
        __syncthreads();             // all warps done with iter j-1 -> stages reusable

        if (tid == 0) {
            if (j + 2 < NITER) {
                int j2 = j + 2, ic2 = j2 >> 4, k2 = j2 & 15, s2 = j2 % 3;
                mbar_expect(MB_B(s2), B_BYTES);
                bulk_g2s(sb + B_OFF + (uint32_t)s2 * BSTG,
                         gwt + ((size_t)(k2 * NIC + ic2) * CO + o0) * 128,
                         B_BYTES, MB_B(s2));
            }
            if (k == 5 && ic + 1 < NIC) {
                int icn = ic + 1;
                mbar_expect(MB_A(icn & 1), A_BYTES);
                bulk_g2s(sb + A_OFF + (uint32_t)(icn & 1) * ABUF,
                         gxt + ((size_t)(b * NIC + icn) * SPAD + t0) * 128,
                         A_BYTES, MB_A(icn & 1));
            }
        }

        // ---- compute iteration j (64 channels = 4 k-steps) ----
        const uint32_t abuf = sb + A_OFF + (uint32_t)(ic & 1) * ABUF;
        const uint32_t bstg = sb + B_OFF + (uint32_t)(j % 3) * BSTG;
        const int ra0 = k + wm * 32 + lm;
        const uint32_t rxa = (uint32_t)((k + lm) & 7) << 4;
        const uint32_t rb0 = (uint32_t)(wn * 64 + bo_row) * 128;
#pragma unroll
        for (int ks = 0; ks < 4; ks++) {
            const uint32_t cba = ((uint32_t)(lg * 16 + ks * 32)) ^ rxa;
            const uint32_t cbb = ((uint32_t)(bhalf * 16 + ks * 32)) ^ rxb;
            uint32_t ah[2][4];
#pragma unroll
            for (int mt = 0; mt < 2; mt++)
                ldm_x4(ah[mt], abuf + (uint32_t)(ra0 + mt * 16) * 128 + cba);
#pragma unroll
            for (int p = 0; p < 4; p++) {
                uint32_t bh[4];
                ldm_x4(bh, bstg + rb0 + (uint32_t)(p * 16) * 128 + cbb);
#pragma unroll
                for (int half = 0; half < 2; half++) {
                    int n = p * 2 + half;
                    const uint32_t* bhp = &bh[half * 2];
#pragma unroll
                    for (int mt = 0; mt < 2; mt++)
                        mma16816(acc[mt][n], ah[mt], bhp);
                }
            }
        }
    }

    // ---- epilogue: direct register -> gmem ----
    const int lr = l >> 2, lc = l & 3;
#pragma unroll
    for (int mt = 0; mt < 2; mt++) {
        int r0 = t0 + wm * 32 + mt * 16 + lr;
        int r1 = r0 + 8;
#pragma unroll
        for (int n = 0; n < 8; n++) {
            int o = o0 + wn * 64 + n * 8 + lc * 2;
            if (r0 < TOUT) {
                float2 v = make_float2(acc[mt][n][0], acc[mt][n][1]);
                *reinterpret_cast<float2*>(out + ((size_t)b * TOUT + r0) * CO + o) = v;
            }
            if (r1 < TOUT) {
                float2 v = make_float2(acc[mt][n][2], acc[mt][n][3]);
                *reinterpret_cast<float2*>(out + ((size_t)b * TOUT + r1) * CO + o) = v;
            }
        }
    }
}

// ---------------- launch ----------------
extern "C" void kernel_launch(void* const* d_in, const int* in_sizes, int n_in,
                              void* d_out, int out_size) {
    const float* x  = (const float*)d_in[0];
    const float* wr = (const float*)d_in[1];
    const float* wi = (const float*)d_in[2];
    const float* ph = (const float*)d_in[3];
    float* out = (float*)d_out;
    (void)in_sizes; (void)n_in; (void)out_size;

    cudaFuncSetAttribute(conv_mma_kernel,
                         cudaFuncAttributeMaxDynamicSharedMemorySize, SMEM_TOTAL);

    prep_kernel<<<XBLOCKS + WBLOCKS, 256>>>(x, wr, wi, ph);

    dim3 grid(SS / MT, NB, CO / NT);   // 16 x 32 x 2 = 1024 CTAs
    conv_mma_kernel<<<grid, 256, SMEM_TOTAL>>>(out);
}

// round 12
// speedup vs baseline: 3.7948x; 1.0561x over previous
#include <cuda_runtime.h>
#include <cuda_fp16.h>
#include <cstdint>

#define NB   32
#define SS   2048
#define SPAD 2064
#define CI   256
#define CO   256
#define KW   16
#define TOUT 2033

#define MT   128
#define NT   128
#define ICH  64
#define NIC  (CI / ICH)    // 4
#define NITER (NIC * KW)   // 64
#define AROWS 143

#define ABUF   18432                 // 144 rows * 128B
#define A_OFF  1024
#define B_OFF  (A_OFF + 2 * ABUF)    // 37888
#define BSTG   16384                 // 128 rows * 128B
#define NSTG   4
#define SMEM_TOTAL (B_OFF + NSTG * BSTG)   // 103424

#define A_BYTES (AROWS * 128)        // 18304
#define B_BYTES (128 * 128)          // 16384

// mbarriers in smem: B stages at +0..+24 ; A bufs at +32,+40
#define MB_B(s) (sb + 8u * (uint32_t)(s))
#define MB_A(p) (sb + 32u + 8u * (uint32_t)(p))

// ---------------- device scratch (pre-swizzled, tile-contiguous) ----------------
__device__ __half g_xt[(size_t)NB * NIC * SPAD * 64];   // [b][ic][t][row 128B, SW128]
__device__ __half g_wt[(size_t)KW * NIC * CO * 64];     // [k][ic][o][row 128B, SW128]

// ---------------- helpers ----------------
__device__ __forceinline__ uint32_t s2u(const void* p) {
    uint32_t a;
    asm("{ .reg .u64 t; cvta.to.shared.u64 t, %1; cvt.u32.u64 %0, t; }"
        : "=r"(a) : "l"(p));
    return a;
}
__device__ __forceinline__ void mbar_init(uint32_t a) {
    asm volatile("mbarrier.init.shared.b64 [%0], 1;" :: "r"(a) : "memory");
}
__device__ __forceinline__ void mbar_expect(uint32_t a, uint32_t bytes) {
    asm volatile("mbarrier.arrive.expect_tx.shared.b64 _, [%0], %1;"
                 :: "r"(a), "r"(bytes) : "memory");
}
__device__ __forceinline__ void bulk_g2s(uint32_t dst, const void* src,
                                         uint32_t bytes, uint32_t mbar) {
    asm volatile(
        "cp.async.bulk.shared::cluster.global.mbarrier::complete_tx::bytes "
        "[%0], [%1], %2, [%3];"
        :: "r"(dst), "l"(src), "r"(bytes), "r"(mbar) : "memory");
}
__device__ __forceinline__ void mbar_wait(uint32_t a, uint32_t parity) {
    asm volatile(
        "{\n\t.reg .pred P;\n\t"
        "WL_%=:\n\t"
        "mbarrier.try_wait.parity.acquire.cta.shared::cta.b64 P, [%0], %1, 0x989680;\n\t"
        "@P bra.uni WD_%=;\n\t"
        "bra.uni WL_%=;\n\t"
        "WD_%=:\n\t}"
        :: "r"(a), "r"(parity) : "memory");
}
__device__ __forceinline__ void ldm_x4(uint32_t* r, uint32_t a) {
    asm volatile("ldmatrix.sync.aligned.m8n8.x4.shared.b16 {%0,%1,%2,%3}, [%4];"
                 : "=r"(r[0]), "=r"(r[1]), "=r"(r[2]), "=r"(r[3]) : "r"(a));
}
__device__ __forceinline__ void mma16816(float* c, const uint32_t* a, const uint32_t* b) {
    asm volatile(
        "mma.sync.aligned.m16n8k16.row.col.f32.f16.f16.f32 "
        "{%0,%1,%2,%3}, {%4,%5,%6,%7}, {%8,%9}, {%0,%1,%2,%3};"
        : "+f"(c[0]), "+f"(c[1]), "+f"(c[2]), "+f"(c[3])
        : "r"(a[0]), "r"(a[1]), "r"(a[2]), "r"(a[3]), "r"(b[0]), "r"(b[1]));
}

// ---------------- fused prep kernel (writes pre-swizzled layouts) ----------------
#define XBLOCKS 16512      // NB*SPAD*CI/4 / 256
#define WBLOCKS 4096       // KW*CO*CI / 256

__global__ void prep_kernel(const float* __restrict__ x,
                            const float* __restrict__ wr,
                            const float* __restrict__ wi,
                            const float* __restrict__ ph) {
    if (blockIdx.x < XBLOCKS) {
        size_t idx4 = (size_t)blockIdx.x * 256 + threadIdx.x;
        size_t idx = idx4 * 4;
        int i = idx & (CI - 1);
        size_t r = idx >> 8;
        int t = (int)(r % SPAD);
        int b = (int)(r / SPAD);
        float4 v = make_float4(0.f, 0.f, 0.f, 0.f);
        if (t < SS)
            v = *reinterpret_cast<const float4*>(x + ((size_t)b * SS + t) * CI + i);
        __half2 h01(__float2half(v.x), __float2half(v.y));
        __half2 h23(__float2half(v.z), __float2half(v.w));
        int ic = i >> 6;
        int cb = (i & 63) * 2;                       // byte col within 128B row
        size_t dst = ((size_t)(b * NIC + ic) * SPAD + t) * 128
                   + (uint32_t)(cb ^ ((t & 7) << 4));
        uint2 u;
        u.x = *reinterpret_cast<uint32_t*>(&h01);
        u.y = *reinterpret_cast<uint32_t*>(&h23);
        *reinterpret_cast<uint2*>(reinterpret_cast<char*>(g_xt) + dst) = u;
    } else {
        int idx = (blockIdx.x - XBLOCKS) * 256 + threadIdx.x;
        int i = idx & (CI - 1);
        int o = (idx >> 8) & (CO - 1);
        int k = idx >> 16;
        float s, c;
        sincosf(ph[k], &s, &c);
        int widx = (o * CI + i) * KW + k;            // w_real/w_imag are [o][i][k]
        float v = c * wr[widx] - s * wi[widx];
        int ic = i >> 6;
        int cb = (i & 63) * 2;
        size_t dst = ((size_t)(k * NIC + ic) * CO + o) * 128
                   + (uint32_t)(cb ^ ((o & 7) << 4));
        *reinterpret_cast<__half*>(reinterpret_cast<char*>(g_wt) + dst) = __float2half(v);
    }
}

// ---------------- main HMMA kernel ----------------
struct Frag { uint32_t ah[2][4]; };

__global__ __launch_bounds__(256, 2)
void conv_mma_kernel(float* __restrict__ out) {
    extern __shared__ char smem[];
    const uint32_t sb = s2u(smem);
    const int tid = threadIdx.x;
    const int l = tid & 31, wid = tid >> 5;
    const int wm = wid & 3, wn = wid >> 2;      // 4(m) x 2(n), warp tile 32x64
    const int t0 = blockIdx.x * MT;
    const int b  = blockIdx.y;
    const int o0 = blockIdx.z * NT;

    const char* gxt = (const char*)g_xt;
    const char* gwt = (const char*)g_wt;

    float acc[2][8][4];
#pragma unroll
    for (int mt = 0; mt < 2; mt++)
#pragma unroll
        for (int n = 0; n < 8; n++)
#pragma unroll
            for (int q = 0; q < 4; q++) acc[mt][n][q] = 0.f;

    const int lm = l & 15;                          // A row within 16
    const int lg = l >> 4;                          // A k-half
    const int bo_row = (l & 7) + ((l >> 4) << 3);   // B o-row within 16
    const int bhalf = (l >> 3) & 1;                 // B k-half
    const uint32_t rxb = (uint32_t)(l & 7) << 4;    // B swizzle term

    if (tid == 0) {
        mbar_init(MB_B(0)); mbar_init(MB_B(1)); mbar_init(MB_B(2)); mbar_init(MB_B(3));
        mbar_init(MB_A(0)); mbar_init(MB_A(1));
    }
    __syncthreads();
    if (tid == 0) {
        mbar_expect(MB_A(0), A_BYTES);
        bulk_g2s(sb + A_OFF,
                 gxt + ((size_t)(b * NIC + 0) * SPAD + t0) * 128, A_BYTES, MB_A(0));
#pragma unroll
        for (int j = 0; j < 2; j++) {              // B tiles 0,1 (ic=0, k=j)
            mbar_expect(MB_B(j), B_BYTES);
            bulk_g2s(sb + B_OFF + (uint32_t)j * BSTG,
                     gwt + ((size_t)(j * NIC) * CO + o0) * 128, B_BYTES, MB_B(j));
        }
    }

    // compute one flat iteration j against B stage `bstg`
    auto compute_iter = [&](int j, uint32_t abuf, uint32_t bstg) {
        const int k = j & 15;
        const int ra0 = k + wm * 32 + lm;
        const uint32_t rxa = (uint32_t)((k + lm) & 7) << 4;
        const uint32_t rb0 = (uint32_t)(wn * 64 + bo_row) * 128;
#pragma unroll
        for (int ks = 0; ks < 4; ks++) {
            const uint32_t cba = ((uint32_t)(lg * 16 + ks * 32)) ^ rxa;
            const uint32_t cbb = ((uint32_t)(bhalf * 16 + ks * 32)) ^ rxb;
            uint32_t ah[2][4];
#pragma unroll
            for (int mt = 0; mt < 2; mt++)
                ldm_x4(ah[mt], abuf + (uint32_t)(ra0 + mt * 16) * 128 + cba);
#pragma unroll
            for (int p = 0; p < 4; p++) {
                uint32_t bh[4];
                ldm_x4(bh, bstg + rb0 + (uint32_t)(p * 16) * 128 + cbb);
#pragma unroll
                for (int half = 0; half < 2; half++) {
                    int n = p * 2 + half;
                    const uint32_t* bhp = &bh[half * 2];
#pragma unroll
                    for (int mt = 0; mt < 2; mt++)
                        mma16816(acc[mt][n], ah[mt], bhp);
                }
            }
        }
    };

    for (int jj = 0; jj < NITER / 2; jj++) {
        const int j0 = jj * 2, j1 = j0 + 1;
        const int ic = j0 >> 4;
        const uint32_t abuf = sb + A_OFF + (uint32_t)(ic & 1) * ABUF;

        if ((j0 & 15) == 0) mbar_wait(MB_A(ic & 1), (ic >> 1) & 1);
        mbar_wait(MB_B(j0 & 3), (j0 >> 2) & 1);
        __syncthreads();             // all warps done with previous pair's stages

        if (tid == 0) {
            // prefetch B for j0+2, j0+3 -> stages (j0+2)&3, (j0+3)&3
#pragma unroll
            for (int d = 2; d < 4; d++) {
                int j2 = j0 + d;
                if (j2 < NITER) {
                    int s2 = j2 & 3;
                    mbar_expect(MB_B(s2), B_BYTES);
                    bulk_g2s(sb + B_OFF + (uint32_t)s2 * BSTG,
                             gwt + ((size_t)((j2 & 15) * NIC + (j2 >> 4)) * CO + o0) * 128,
                             B_BYTES, MB_B(s2));
                }
            }
            if ((j0 & 15) == 4 && ic + 1 < NIC) {
                int icn = ic + 1;
                mbar_expect(MB_A(icn & 1), A_BYTES);
                bulk_g2s(sb + A_OFF + (uint32_t)(icn & 1) * ABUF,
                         gxt + ((size_t)(b * NIC + icn) * SPAD + t0) * 128,
                         A_BYTES, MB_A(icn & 1));
            }
        }

        compute_iter(j0, abuf, sb + B_OFF + (uint32_t)(j0 & 3) * BSTG);
        mbar_wait(MB_B(j1 & 3), (j1 >> 2) & 1);     // overlapped by j0 compute
        compute_iter(j1, abuf, sb + B_OFF + (uint32_t)(j1 & 3) * BSTG);
    }

    // ---- epilogue: direct register -> gmem ----
    const int lr = l >> 2, lc = l & 3;
#pragma unroll
    for (int mt = 0; mt < 2; mt++) {
        int r0 = t0 + wm * 32 + mt * 16 + lr;
        int r1 = r0 + 8;
#pragma unroll
        for (int n = 0; n < 8; n++) {
            int o = o0 + wn * 64 + n * 8 + lc * 2;
            if (r0 < TOUT) {
                float2 v = make_float2(acc[mt][n][0], acc[mt][n][1]);
                *reinterpret_cast<float2*>(out + ((size_t)b * TOUT + r0) * CO + o) = v;
            }
            if (r1 < TOUT) {
                float2 v = make_float2(acc[mt][n][2], acc[mt][n][3]);
                *reinterpret_cast<float2*>(out + ((size_t)b * TOUT + r1) * CO + o) = v;
            }
        }
    }
}

// ---------------- launch ----------------
extern "C" void kernel_launch(void* const* d_in, const int* in_sizes, int n_in,
                              void* d_out, int out_size) {
    const float* x  = (const float*)d_in[0];
    const float* wr = (const float*)d_in[1];
    const float* wi = (const float*)d_in[2];
    const float* ph = (const float*)d_in[3];
    float* out = (float*)d_out;
    (void)in_sizes; (void)n_in; (void)out_size;

    cudaFuncSetAttribute(conv_mma_kernel,
                         cudaFuncAttributeMaxDynamicSharedMemorySize, SMEM_TOTAL);

    prep_kernel<<<XBLOCKS + WBLOCKS, 256>>>(x, wr, wi, ph);

    dim3 grid(SS / MT, NB, CO / NT);   // 16 x 32 x 2 = 1024 CTAs
    conv_mma_kernel<<<grid, 256, SMEM_TOTAL>>>(out);
}